// round 15
// baseline (speedup 1.0000x reference)
#include <cuda_runtime.h>
#include <cuda_fp16.h>
#include <cstdint>
#include <cstddef>

// Problem: B=64, T=512, F=1024
//   stats over all x; y = x*scale + shift
//   out[b,t,f] = x[b,t,f] + relu( sum_t' y[b,t',f]*W[t,t'] + bias[t] )
// Refactor: h[u,f] = scale * (sum_t' x[t',f]*W[u,t']) + shift*wsum[u]
// GEMM on raw fp16 x-transpose vs fp16 W; normalization folded into epilogue.
// Stats finalize is computed redundantly per GEMM CTA from L2-resident
// partials (deterministic, identical result in every CTA) -> 2 launches only.

#define BSZ  64
#define TDIM 512
#define FDIM 1024
#define NTOT (BSZ * TDIM * FDIM)
#define EPSV 1e-5f

#define CT_BLOCKS (8 * 32 * BSZ)   // convert main slice: (T/64, F/32, B) = 16384

__device__ float g_partial[2 * CT_BLOCKS];
__device__ float g_wsum[TDIM];               // fp32 row sums of W

__device__ __align__(16) __half g_xT[(size_t)BSZ * FDIM * TDIM];  // [b][f][t]
__device__ __align__(16) __half g_w_h[TDIM * TDIM];               // [u][t]

// ---------------------------------------------------------------------------
__device__ __forceinline__ uint32_t smem_u32(const void* p) {
    uint32_t a;
    asm("{ .reg .u64 t; cvta.to.shared.u64 t, %1; cvt.u32.u64 %0, t; }"
        : "=r"(a) : "l"(p));
    return a;
}
__device__ __forceinline__ void cp16(uint32_t s, const void* g) {
    asm volatile("cp.async.cg.shared.global [%0], [%1], 16;" :: "r"(s), "l"(g) : "memory");
}
__device__ __forceinline__ void ldsm4(uint32_t* r, uint32_t addr) {
    asm volatile("ldmatrix.sync.aligned.m8n8.x4.shared.b16 {%0,%1,%2,%3}, [%4];"
                 : "=r"(r[0]), "=r"(r[1]), "=r"(r[2]), "=r"(r[3]) : "r"(addr));
}
__device__ __forceinline__ void mma16816(float* c, const uint32_t* a, const uint32_t* b) {
    asm volatile("mma.sync.aligned.m16n8k16.row.col.f32.f16.f16.f32 "
                 "{%0,%1,%2,%3}, {%4,%5,%6,%7}, {%8,%9}, {%0,%1,%2,%3};"
                 : "+f"(c[0]), "+f"(c[1]), "+f"(c[2]), "+f"(c[3])
                 : "r"(a[0]), "r"(a[1]), "r"(a[2]), "r"(a[3]), "r"(b[0]), "r"(b[1]));
}

// ---------------------------------------------------------------------------
// Kernel 1: fused transpose-to-fp16 + stats partials (x read ONCE),
// plus a W-prep slice (blockIdx.z == BSZ). FLAT 256-thread block.
// (identical to Round-14 passing version)
// ---------------------------------------------------------------------------
__global__ __launch_bounds__(256)
void convert_reduce(const float* __restrict__ x, const float* __restrict__ W) {
    __shared__ float tile[64 * 32];
    __shared__ float ws0[8], ws1[8];
    const int tid = threadIdx.x;                 // FLAT 0..255
    const int wid = tid >> 5, lid = tid & 31;

    if (blockIdx.z == BSZ) {
        const int idx = blockIdx.x + 8 * blockIdx.y;   // 0..255
#pragma unroll
        for (int r = 0; r < 2; r++) {
            const int u = idx * 2 + r;
            float s = 0.f;
#pragma unroll
            for (int q = 0; q < 2; q++) {
                const int t = q * 256 + tid;
                float w = W[(size_t)u * TDIM + t];
                g_w_h[(size_t)u * TDIM + t] = __float2half_rn(w);
                s += w;
            }
#pragma unroll
            for (int o = 16; o > 0; o >>= 1)
                s += __shfl_xor_sync(0xFFFFFFFFu, s, o);
            if (lid == 0) ws0[wid] = s;
            __syncthreads();
            if (tid < 8) {
                float a0 = ws0[tid];
#pragma unroll
                for (int o = 4; o > 0; o >>= 1)
                    a0 += __shfl_xor_sync(0x000000FFu, a0, o);
                if (tid == 0) g_wsum[u] = a0;
            }
            __syncthreads();
        }
        return;
    }

    const int b = blockIdx.z, t0 = blockIdx.x * 64, f0 = blockIdx.y * 32;
    const float* __restrict__ xb = x + ((size_t)b * TDIM + t0) * FDIM + f0;

    float s = 0.f, ss = 0.f;
#pragma unroll
    for (int j = 0; j < 2; j++) {
        const int r = (tid >> 3) + j * 32;        // t row 0..63
        const int c = tid & 7;                    // f float4-group 0..7
        float4 v = *(const float4*)(xb + (size_t)r * FDIM + c * 4);
        const int slot = c ^ ((r >> 3) & 7);      // XOR swizzle
        *(float4*)&tile[r * 32 + slot * 4] = v;
        s  += (v.x + v.y) + (v.z + v.w);
        ss += (v.x * v.x + v.y * v.y) + (v.z * v.z + v.w * v.w);
    }
#pragma unroll
    for (int o = 16; o > 0; o >>= 1) {
        s  += __shfl_xor_sync(0xFFFFFFFFu, s,  o);
        ss += __shfl_xor_sync(0xFFFFFFFFu, ss, o);
    }
    if (lid == 0) { ws0[wid] = s; ws1[wid] = ss; }
    __syncthreads();

    const int fl = tid >> 3;          // f 0..31
    const int m  = tid & 7;           // t-block 0..7 -> t = m*8+q
    const int base = ((fl >> 2) ^ m) * 4 + (fl & 3);   // swizzled column word
    __half hv[8];
#pragma unroll
    for (int q = 0; q < 8; q++)
        hv[q] = __float2half_rn(tile[(m * 8 + q) * 32 + base]);
    __half* __restrict__ ph = g_xT + ((size_t)b * FDIM + f0 + fl) * TDIM + t0 + m * 8;
    *(uint4*)ph = *(const uint4*)hv;

    if (tid < 8) {
        float a0 = ws0[tid], a1 = ws1[tid];
#pragma unroll
        for (int o = 4; o > 0; o >>= 1) {
            a0 += __shfl_xor_sync(0x000000FFu, a0, o);
            a1 += __shfl_xor_sync(0x000000FFu, a1, o);
        }
        if (tid == 0) {
            const int blin = blockIdx.x + 8 * (blockIdx.y + 32 * blockIdx.z);
            g_partial[blin]             = a0;
            g_partial[CT_BLOCKS + blin] = a1;
        }
    }
}

// ---------------------------------------------------------------------------
// Kernel 2: fp16 mma.sync GEMM + fused epilogue (Round-7 mainloop, unchanged)
// + per-CTA stats finalize from L2-resident partials (deterministic).
// CTA 128(f) x 64(u), BK=32, KITER=16, 4-stage cp.async pipeline.
// 8 warps as 4(m) x 2(n); warp tile 32x32. 3 CTAs/SM.
// ---------------------------------------------------------------------------
#define GM 128
#define GN 64
#define GBK 32
#define KITER 16            // 512 / 32
#define ROWB 80             // 32 fp16 (64B) + 16B pad

#define PL_A     (GM * ROWB)            // 10240
#define PL_B     (GN * ROWB)            // 5120
#define STAGE_SZ (PL_A + PL_B)          // 15360
#define SMEM_SZ  (4 * STAGE_SZ)         // 61440 (epilogue reuse: 64*132*4=33792)

__global__ __launch_bounds__(256, 3)
void gemm_tc(const float* __restrict__ x, const float* __restrict__ bias,
             const float* __restrict__ gamma, const float* __restrict__ beta,
             float* __restrict__ out) {
    extern __shared__ char smem[];
    const uint32_t sb = smem_u32(smem);
    const int tid = threadIdx.x, wid = tid >> 5, lid = tid & 31;
    const int wm = wid >> 1, wn = wid & 1;           // 4 x 2 warp grid
    const int b = blockIdx.z, f0 = blockIdx.x * GM, u0 = blockIdx.y * GN;

    const __half* __restrict__ Ap = g_xT + ((size_t)b * FDIM + f0) * TDIM;
    const __half* __restrict__ Bp = g_w_h + (size_t)u0 * TDIM;

    const int ar0 = tid >> 2, ac0 = tid & 3;
    const int ar1 = (tid + 256) >> 2;
    const int br0 = tid >> 2, bc0 = tid & 3;
    const uint32_t aso0 = (uint32_t)(ar0 * ROWB + ac0 * 16);
    const uint32_t aso1 = (uint32_t)(ar1 * ROWB + ac0 * 16);
    const uint32_t bso0 = (uint32_t)(br0 * ROWB + bc0 * 16);
    const size_t ago0 = (size_t)ar0 * TDIM + ac0 * 8;
    const size_t ago1 = (size_t)ar1 * TDIM + ac0 * 8;
    const size_t bgo0 = (size_t)br0 * TDIM + bc0 * 8;

    const uint32_t a_off = (uint32_t)((wm * 32 + (lid & 15)) * ROWB + (lid >> 4) * 16);
    const uint32_t b_off = (uint32_t)((wn * 32 + (lid & 7) + ((lid >> 4) * 8)) * ROWB
                                      + ((lid >> 3) & 1) * 16);

    float acc[2][4][4];
#pragma unroll
    for (int i = 0; i < 2; i++)
#pragma unroll
        for (int j = 0; j < 4; j++)
#pragma unroll
            for (int q = 0; q < 4; q++) acc[i][j][q] = 0.f;

#pragma unroll
    for (int s = 0; s < 3; s++) {
        const uint32_t st = sb + s * STAGE_SZ;
        const size_t g = (size_t)s * GBK;
        cp16(st + aso0,        Ap + ago0 + g);
        cp16(st + aso1,        Ap + ago1 + g);
        cp16(st + PL_A + bso0, Bp + bgo0 + g);
        asm volatile("cp.async.commit_group;" ::: "memory");
    }

    for (int kc = 0; kc < KITER; kc++) {
        if (kc < KITER - 2)
            asm volatile("cp.async.wait_group 2;" ::: "memory");
        else if (kc == KITER - 2)
            asm volatile("cp.async.wait_group 1;" ::: "memory");
        else
            asm volatile("cp.async.wait_group 0;" ::: "memory");
        __syncthreads();

        if (kc + 3 < KITER) {
            const uint32_t st = sb + ((kc + 3) & 3) * STAGE_SZ;
            const size_t g = (size_t)(kc + 3) * GBK;
            cp16(st + aso0,        Ap + ago0 + g);
            cp16(st + aso1,        Ap + ago1 + g);
            cp16(st + PL_A + bso0, Bp + bgo0 + g);
            asm volatile("cp.async.commit_group;" ::: "memory");
        }

        const uint32_t st = sb + (kc & 3) * STAGE_SZ;
#pragma unroll
        for (int ks = 0; ks < 2; ks++) {
            const uint32_t kb = ks * 32;     // 16 elems * 2B
            uint32_t ah[2][4], bh[2][4];
#pragma unroll
            for (int mt = 0; mt < 2; mt++)
                ldsm4(ah[mt], st + a_off + mt * (16 * ROWB) + kb);
#pragma unroll
            for (int nt = 0; nt < 2; nt++)
                ldsm4(bh[nt], st + PL_A + b_off + nt * (16 * ROWB) + kb);
#pragma unroll
            for (int mt = 0; mt < 2; mt++)
#pragma unroll
                for (int nf = 0; nf < 4; nf++)
                    mma16816(acc[mt][nf], ah[mt], &bh[nf >> 1][(nf & 1) * 2]);
        }
    }
    __syncthreads();

    // ---- per-CTA stats finalize (L2-resident partials; deterministic) ----
    float* __restrict__ S = (float*)smem;     // reuse pipeline smem
    {
        float s = 0.f, ss = 0.f;
#pragma unroll
        for (int q = 0; q < CT_BLOCKS / 256; q++) {
            s  += __ldg(&g_partial[q * 256 + tid]);
            ss += __ldg(&g_partial[CT_BLOCKS + q * 256 + tid]);
        }
#pragma unroll
        for (int o = 16; o > 0; o >>= 1) {
            s  += __shfl_xor_sync(0xFFFFFFFFu, s,  o);
            ss += __shfl_xor_sync(0xFFFFFFFFu, ss, o);
        }
        if (lid == 0) { S[wid] = s; S[8 + wid] = ss; }
        __syncthreads();
        if (tid < 8) {
            float a0 = S[tid], a1 = S[8 + tid];
#pragma unroll
            for (int o = 4; o > 0; o >>= 1) {
                a0 += __shfl_xor_sync(0x000000FFu, a0, o);
                a1 += __shfl_xor_sync(0x000000FFu, a1, o);
            }
            if (tid == 0) {
                const float invN = 1.0f / (float)NTOT;
                float mean = a0 * invN;
                float var  = a1 * invN - mean * mean;
                float sc = __ldg(&gamma[0]) * rsqrtf(var + EPSV);
                S[16] = sc;
                S[17] = __ldg(&beta[0]) - mean * sc;
            }
        }
        __syncthreads();
    }
    const float scale = S[16], shift = S[17];
    __syncthreads();   // all threads have read S[16..17] before S is overwritten

    // ---- epilogue: transpose via smem, h = scale*acc + shift*wsum[u] + bias[u]
    const int qrow = lid >> 2, qcol = (lid & 3) * 2;
#pragma unroll
    for (int mt = 0; mt < 2; mt++)
#pragma unroll
        for (int nf = 0; nf < 4; nf++) {
            const int fl = wm * 32 + mt * 16 + qrow;
            const int ul = wn * 32 + nf * 8 + qcol;
            S[(ul)     * 132 + fl]     = acc[mt][nf][0];
            S[(ul + 1) * 132 + fl]     = acc[mt][nf][1];
            S[(ul)     * 132 + fl + 8] = acc[mt][nf][2];
            S[(ul + 1) * 132 + fl + 8] = acc[mt][nf][3];
        }
    __syncthreads();

    const int fl4 = (tid & 31) * 4, ur = tid >> 5;
#pragma unroll
    for (int up = 0; up < 8; up++) {
        const int ul = up * 8 + ur;
        const int u = u0 + ul;
        const float cu = shift * g_wsum[u] + __ldg(&bias[u]);
        const size_t gidx = ((size_t)b * TDIM + u) * FDIM + f0 + fl4;
        float4 xv = *(const float4*)(x + gidx);
        const float* sp = S + ul * 132 + fl4;
        float4 o;
        o.x = xv.x + fmaxf(fmaf(scale, sp[0], cu), 0.f);
        o.y = xv.y + fmaxf(fmaf(scale, sp[1], cu), 0.f);
        o.z = xv.z + fmaxf(fmaf(scale, sp[2], cu), 0.f);
        o.w = xv.w + fmaxf(fmaf(scale, sp[3], cu), 0.f);
        *(float4*)(out + gidx) = o;
    }
}

// ---------------------------------------------------------------------------
extern "C" void kernel_launch(void* const* d_in, const int* in_sizes, int n_in,
                              void* d_out, int out_size) {
    const float* x     = (const float*)d_in[0];
    const float* W     = (const float*)d_in[1];
    const float* bias  = (const float*)d_in[2];
    const float* gamma = (const float*)d_in[3];
    const float* beta  = (const float*)d_in[4];
    float* out = (float*)d_out;

    static bool attr_set = false;
    if (!attr_set) {
        cudaFuncSetAttribute(gemm_tc, cudaFuncAttributeMaxDynamicSharedMemorySize, SMEM_SZ);
        attr_set = true;
    }

    // main slice (z<64) transposes x; z==64 slice preps W (rides along free)
    convert_reduce<<<dim3(8, 32, BSZ + 1), 256>>>(x, W);

    dim3 grid(FDIM / GM, TDIM / GN, BSZ);
    gemm_tc<<<grid, 256, SMEM_SZ>>>(x, bias, gamma, beta, out);
}

// round 16
// speedup vs baseline: 1.1235x; 1.1235x over previous
#include <cuda_runtime.h>
#include <cuda_fp16.h>
#include <cstdint>
#include <cstddef>

// Problem: B=64, T=512, F=1024
//   stats over all x; y = x*scale + shift
//   out[b,t,f] = x[b,t,f] + relu( sum_t' y[b,t',f]*W[t,t'] + bias[t] )
// Refactor: h[u,f] = scale * (sum_t' x[t',f]*W[u,t']) + shift*wsum[u]
// GEMM on raw fp16 x-transpose vs fp16 W; normalization folded into epilogue.

#define BSZ  64
#define TDIM 512
#define FDIM 1024
#define NTOT (BSZ * TDIM * FDIM)
#define EPSV 1e-5f

#define CT_BLOCKS (8 * 16 * BSZ)   // convert main slice: (T/64, F/64, B) = 8192

__device__ float g_partial[2 * CT_BLOCKS];
__device__ float g_stats[2];                 // {scale, shift}
__device__ float g_wsum[TDIM];               // fp32 row sums of W

__device__ __align__(16) __half g_xT[(size_t)BSZ * FDIM * TDIM];  // [b][f][t]
__device__ __align__(16) __half g_w_h[TDIM * TDIM];               // [u][t]

// ---------------------------------------------------------------------------
__device__ __forceinline__ uint32_t smem_u32(const void* p) {
    uint32_t a;
    asm("{ .reg .u64 t; cvta.to.shared.u64 t, %1; cvt.u32.u64 %0, t; }"
        : "=r"(a) : "l"(p));
    return a;
}
__device__ __forceinline__ void cp16(uint32_t s, const void* g) {
    asm volatile("cp.async.cg.shared.global [%0], [%1], 16;" :: "r"(s), "l"(g) : "memory");
}
__device__ __forceinline__ void ldsm4(uint32_t* r, uint32_t addr) {
    asm volatile("ldmatrix.sync.aligned.m8n8.x4.shared.b16 {%0,%1,%2,%3}, [%4];"
                 : "=r"(r[0]), "=r"(r[1]), "=r"(r[2]), "=r"(r[3]) : "r"(addr));
}
__device__ __forceinline__ void mma16816(float* c, const uint32_t* a, const uint32_t* b) {
    asm volatile("mma.sync.aligned.m16n8k16.row.col.f32.f16.f16.f32 "
                 "{%0,%1,%2,%3}, {%4,%5,%6,%7}, {%8,%9}, {%0,%1,%2,%3};"
                 : "+f"(c[0]), "+f"(c[1]), "+f"(c[2]), "+f"(c[3])
                 : "r"(a[0]), "r"(a[1]), "r"(a[2]), "r"(a[3]), "r"(b[0]), "r"(b[1]));
}

// ---------------------------------------------------------------------------
// Kernel 1: fused transpose-to-fp16 + stats partials (x read ONCE),
// plus a W-prep slice (blockIdx.z == BSZ). FLAT 256-thread block.
// Main slice: 64(t) x 64(f) tile as TWO 64x32 half-tiles in a double smem
// buffer (ONE __syncthreads). Same proven float4/XOR-swizzle mappings.
// ---------------------------------------------------------------------------
__global__ __launch_bounds__(256)
void convert_reduce(const float* __restrict__ x, const float* __restrict__ W) {
    __shared__ float tile[2][64 * 32];
    __shared__ float ws0[8], ws1[8];
    const int tid = threadIdx.x;                 // FLAT 0..255
    const int wid = tid >> 5, lid = tid & 31;

    if (blockIdx.z == BSZ) {
        // ---- W-prep slice: 128 blocks x 4 rows each ----
        const int idx = blockIdx.x + 8 * blockIdx.y;   // 0..127
#pragma unroll
        for (int r = 0; r < 4; r++) {
            const int u = idx * 4 + r;
            float s = 0.f;
#pragma unroll
            for (int q = 0; q < 2; q++) {
                const int t = q * 256 + tid;
                float w = W[(size_t)u * TDIM + t];
                g_w_h[(size_t)u * TDIM + t] = __float2half_rn(w);
                s += w;
            }
#pragma unroll
            for (int o = 16; o > 0; o >>= 1)
                s += __shfl_xor_sync(0xFFFFFFFFu, s, o);
            if (lid == 0) ws0[wid] = s;
            __syncthreads();
            if (tid < 8) {
                float a0 = ws0[tid];
#pragma unroll
                for (int o = 4; o > 0; o >>= 1)
                    a0 += __shfl_xor_sync(0x000000FFu, a0, o);
                if (tid == 0) g_wsum[u] = a0;
            }
            __syncthreads();
        }
        return;
    }

    // ---- main slice: transpose + partial stats over a 64x64 tile ----
    const int b = blockIdx.z, t0 = blockIdx.x * 64, f0 = blockIdx.y * 64;
    const float* __restrict__ xb = x + ((size_t)b * TDIM + t0) * FDIM + f0;

    float s = 0.f, ss = 0.f;
#pragma unroll
    for (int h = 0; h < 2; h++) {
#pragma unroll
        for (int j = 0; j < 2; j++) {
            const int r = (tid >> 3) + j * 32;        // t row 0..63
            const int c = tid & 7;                    // f float4-group 0..7
            float4 v = *(const float4*)(xb + (size_t)r * FDIM + h * 32 + c * 4);
            const int slot = c ^ ((r >> 3) & 7);      // XOR swizzle
            *(float4*)&tile[h][r * 32 + slot * 4] = v;
            s  += (v.x + v.y) + (v.z + v.w);
            ss += (v.x * v.x + v.y * v.y) + (v.z * v.z + v.w * v.w);
        }
    }
#pragma unroll
    for (int o = 16; o > 0; o >>= 1) {
        s  += __shfl_xor_sync(0xFFFFFFFFu, s,  o);
        ss += __shfl_xor_sync(0xFFFFFFFFu, ss, o);
    }
    if (lid == 0) { ws0[wid] = s; ws1[wid] = ss; }
    __syncthreads();

    // transpose-store fp16: 8 lanes cover one 128B row segment (coalesced)
    const int fl = tid >> 3;          // f 0..31 within half-tile
    const int m  = tid & 7;           // t-block 0..7 -> t = m*8+q
    const int base = ((fl >> 2) ^ m) * 4 + (fl & 3);   // swizzled column word
#pragma unroll
    for (int h = 0; h < 2; h++) {
        __half hv[8];
#pragma unroll
        for (int q = 0; q < 8; q++)
            hv[q] = __float2half_rn(tile[h][(m * 8 + q) * 32 + base]);
        __half* __restrict__ ph =
            g_xT + ((size_t)b * FDIM + f0 + h * 32 + fl) * TDIM + t0 + m * 8;
        *(uint4*)ph = *(const uint4*)hv;
    }

    if (tid < 8) {
        float a0 = ws0[tid], a1 = ws1[tid];
#pragma unroll
        for (int o = 4; o > 0; o >>= 1) {
            a0 += __shfl_xor_sync(0x000000FFu, a0, o);
            a1 += __shfl_xor_sync(0x000000FFu, a1, o);
        }
        if (tid == 0) {
            const int blin = blockIdx.x + 8 * (blockIdx.y + 16 * blockIdx.z);
            g_partial[blin]             = a0;
            g_partial[CT_BLOCKS + blin] = a1;
        }
    }
}

// ---------------------------------------------------------------------------
// Kernel 2: stats finalize (single block, 1024 threads)
// ---------------------------------------------------------------------------
__global__ __launch_bounds__(1024)
void finalize_stats(const float* __restrict__ gamma,
                    const float* __restrict__ beta) {
    const int tid = threadIdx.x;   // 1024
    float s = 0.f, ss = 0.f;
#pragma unroll
    for (int q = 0; q < CT_BLOCKS / 1024; q++) {
        s  += g_partial[q * 1024 + tid];
        ss += g_partial[CT_BLOCKS + q * 1024 + tid];
    }
#pragma unroll
    for (int o = 16; o > 0; o >>= 1) {
        s  += __shfl_xor_sync(0xFFFFFFFFu, s,  o);
        ss += __shfl_xor_sync(0xFFFFFFFFu, ss, o);
    }
    __shared__ float sh0[32], sh1[32];
    const int wid = tid >> 5, lid = tid & 31;
    if (lid == 0) { sh0[wid] = s; sh1[wid] = ss; }
    __syncthreads();
    if (tid < 32) {
        float a0 = sh0[tid], a1 = sh1[tid];
#pragma unroll
        for (int o = 16; o > 0; o >>= 1) {
            a0 += __shfl_xor_sync(0xFFFFFFFFu, a0, o);
            a1 += __shfl_xor_sync(0xFFFFFFFFu, a1, o);
        }
        if (tid == 0) {
            const float invN = 1.0f / (float)NTOT;
            float mean = a0 * invN;
            float var  = a1 * invN - mean * mean;
            float scale = gamma[0] * rsqrtf(var + EPSV);
            g_stats[0] = scale;
            g_stats[1] = beta[0] - mean * scale;
        }
    }
}

// ---------------------------------------------------------------------------
// Kernel 3: fp16 mma.sync GEMM + fused epilogue  (Round-7 best, unchanged)
// CTA 128(f) x 64(u), BK=32, KITER=16, 4-stage cp.async pipeline.
// 8 warps as 4(m) x 2(n); warp tile 32x32. 3 CTAs/SM.
// ---------------------------------------------------------------------------
#define GM 128
#define GN 64
#define GBK 32
#define KITER 16            // 512 / 32
#define ROWB 80             // 32 fp16 (64B) + 16B pad

#define PL_A     (GM * ROWB)            // 10240
#define PL_B     (GN * ROWB)            // 5120
#define STAGE_SZ (PL_A + PL_B)          // 15360
#define SMEM_SZ  (4 * STAGE_SZ)         // 61440 (epilogue reuse: 64*132*4=33792)

__global__ __launch_bounds__(256, 3)
void gemm_tc(const float* __restrict__ x, const float* __restrict__ bias,
             float* __restrict__ out) {
    extern __shared__ char smem[];
    const uint32_t sb = smem_u32(smem);
    const int tid = threadIdx.x, wid = tid >> 5, lid = tid & 31;
    const int wm = wid >> 1, wn = wid & 1;           // 4 x 2 warp grid
    const int b = blockIdx.z, f0 = blockIdx.x * GM, u0 = blockIdx.y * GN;

    const __half* __restrict__ Ap = g_xT + ((size_t)b * FDIM + f0) * TDIM;
    const __half* __restrict__ Bp = g_w_h + (size_t)u0 * TDIM;

    const int ar0 = tid >> 2, ac0 = tid & 3;
    const int ar1 = (tid + 256) >> 2;
    const int br0 = tid >> 2, bc0 = tid & 3;
    const uint32_t aso0 = (uint32_t)(ar0 * ROWB + ac0 * 16);
    const uint32_t aso1 = (uint32_t)(ar1 * ROWB + ac0 * 16);
    const uint32_t bso0 = (uint32_t)(br0 * ROWB + bc0 * 16);
    const size_t ago0 = (size_t)ar0 * TDIM + ac0 * 8;
    const size_t ago1 = (size_t)ar1 * TDIM + ac0 * 8;
    const size_t bgo0 = (size_t)br0 * TDIM + bc0 * 8;

    const uint32_t a_off = (uint32_t)((wm * 32 + (lid & 15)) * ROWB + (lid >> 4) * 16);
    const uint32_t b_off = (uint32_t)((wn * 32 + (lid & 7) + ((lid >> 4) * 8)) * ROWB
                                      + ((lid >> 3) & 1) * 16);

    float acc[2][4][4];
#pragma unroll
    for (int i = 0; i < 2; i++)
#pragma unroll
        for (int j = 0; j < 4; j++)
#pragma unroll
            for (int q = 0; q < 4; q++) acc[i][j][q] = 0.f;

#pragma unroll
    for (int s = 0; s < 3; s++) {
        const uint32_t st = sb + s * STAGE_SZ;
        const size_t g = (size_t)s * GBK;
        cp16(st + aso0,        Ap + ago0 + g);
        cp16(st + aso1,        Ap + ago1 + g);
        cp16(st + PL_A + bso0, Bp + bgo0 + g);
        asm volatile("cp.async.commit_group;" ::: "memory");
    }

    for (int kc = 0; kc < KITER; kc++) {
        if (kc < KITER - 2)
            asm volatile("cp.async.wait_group 2;" ::: "memory");
        else if (kc == KITER - 2)
            asm volatile("cp.async.wait_group 1;" ::: "memory");
        else
            asm volatile("cp.async.wait_group 0;" ::: "memory");
        __syncthreads();

        if (kc + 3 < KITER) {
            const uint32_t st = sb + ((kc + 3) & 3) * STAGE_SZ;
            const size_t g = (size_t)(kc + 3) * GBK;
            cp16(st + aso0,        Ap + ago0 + g);
            cp16(st + aso1,        Ap + ago1 + g);
            cp16(st + PL_A + bso0, Bp + bgo0 + g);
            asm volatile("cp.async.commit_group;" ::: "memory");
        }

        const uint32_t st = sb + (kc & 3) * STAGE_SZ;
#pragma unroll
        for (int ks = 0; ks < 2; ks++) {
            const uint32_t kb = ks * 32;     // 16 elems * 2B
            uint32_t ah[2][4], bh[2][4];
#pragma unroll
            for (int mt = 0; mt < 2; mt++)
                ldsm4(ah[mt], st + a_off + mt * (16 * ROWB) + kb);
#pragma unroll
            for (int nt = 0; nt < 2; nt++)
                ldsm4(bh[nt], st + PL_A + b_off + nt * (16 * ROWB) + kb);
#pragma unroll
            for (int mt = 0; mt < 2; mt++)
#pragma unroll
                for (int nf = 0; nf < 4; nf++)
                    mma16816(acc[mt][nf], ah[mt], &bh[nf >> 1][(nf & 1) * 2]);
        }
    }
    __syncthreads();

    const float scale = g_stats[0], shift = g_stats[1];
    float* __restrict__ S = (float*)smem;     // [u_local][f_local], stride 132
    const int qrow = lid >> 2, qcol = (lid & 3) * 2;
#pragma unroll
    for (int mt = 0; mt < 2; mt++)
#pragma unroll
        for (int nf = 0; nf < 4; nf++) {
            const int fl = wm * 32 + mt * 16 + qrow;
            const int ul = wn * 32 + nf * 8 + qcol;
            S[(ul)     * 132 + fl]     = acc[mt][nf][0];
            S[(ul + 1) * 132 + fl]     = acc[mt][nf][1];
            S[(ul)     * 132 + fl + 8] = acc[mt][nf][2];
            S[(ul + 1) * 132 + fl + 8] = acc[mt][nf][3];
        }
    __syncthreads();

    const int fl4 = (tid & 31) * 4, ur = tid >> 5;
#pragma unroll
    for (int up = 0; up < 8; up++) {
        const int ul = up * 8 + ur;
        const int u = u0 + ul;
        const float cu = shift * g_wsum[u] + __ldg(&bias[u]);
        const size_t gidx = ((size_t)b * TDIM + u) * FDIM + f0 + fl4;
        float4 xv = *(const float4*)(x + gidx);
        const float* sp = S + ul * 132 + fl4;
        float4 o;
        o.x = xv.x + fmaxf(fmaf(scale, sp[0], cu), 0.f);
        o.y = xv.y + fmaxf(fmaf(scale, sp[1], cu), 0.f);
        o.z = xv.z + fmaxf(fmaf(scale, sp[2], cu), 0.f);
        o.w = xv.w + fmaxf(fmaf(scale, sp[3], cu), 0.f);
        *(float4*)(out + gidx) = o;
    }
}

// ---------------------------------------------------------------------------
extern "C" void kernel_launch(void* const* d_in, const int* in_sizes, int n_in,
                              void* d_out, int out_size) {
    const float* x     = (const float*)d_in[0];
    const float* W     = (const float*)d_in[1];
    const float* bias  = (const float*)d_in[2];
    const float* gamma = (const float*)d_in[3];
    const float* beta  = (const float*)d_in[4];
    float* out = (float*)d_out;

    static bool attr_set = false;
    if (!attr_set) {
        cudaFuncSetAttribute(gemm_tc, cudaFuncAttributeMaxDynamicSharedMemorySize, SMEM_SZ);
        attr_set = true;
    }

    // main slice (z<64) transposes x; z==64 slice preps W (rides along free)
    convert_reduce<<<dim3(8, 16, BSZ + 1), 256>>>(x, W);
    finalize_stats<<<1, 1024>>>(gamma, beta);

    dim3 grid(FDIM / GM, TDIM / GN, BSZ);
    gemm_tc<<<grid, 256, SMEM_SZ>>>(x, bias, out);
}